// round 13
// baseline (speedup 1.0000x reference)
#include <cuda_runtime.h>
#include <cuda_bf16.h>
#include <math.h>
#include <stdint.h>

// Problem dims (fixed by the dataset)
#define NN 50000   // nodes
#define KK 10      // sampled neighbors (sequence length)
#define FF 128     // input_dim
#define HH 64      // hidden per direction
#define GG 256     // 4*H gates
#define MF (NN*KK) // 500000 projection rows (forward)

// Scratch (device globals — no allocation allowed)
__device__ float g_xg [(size_t)MF * GG];  // [N*K, 256] forward input projections (+bias)
__device__ float g_xgb[(size_t)NN * GG];  // [N, 256]   backward-last-step projections (+bias)
// bf16 hi/lo split weight copies: [0]=forward Wih, [1]=backward Wih
__device__ __nv_bfloat16 g_Wh[2][GG * FF];
__device__ __nv_bfloat16 g_Wl[2][GG * FF];
// bf16 hi/lo split of Whh_f [256][64]
__device__ __nv_bfloat16 g_Whh_h[GG * HH];
__device__ __nv_bfloat16 g_Whh_l[GG * HH];

__device__ __forceinline__ float sigf(float x) {
    return 1.f / (1.f + __expf(-x));
}
__device__ __forceinline__ float tanh_fast(float x) {
    float e = __expf(2.f * x);
    return 1.f - 2.f / (e + 1.f);
}
__device__ __forceinline__ uint32_t pack2bf(__nv_bfloat16 a, __nv_bfloat16 b) {
    return ((uint32_t)__bfloat16_as_ushort(b) << 16) | __bfloat16_as_ushort(a);
}

// warp-level bf16 HMMA (portable PTX, no sm_103a-only features)
__device__ __forceinline__ void mma16816(float* c, const uint32_t* a,
                                         uint32_t b0, uint32_t b1) {
    asm volatile(
        "mma.sync.aligned.m16n8k16.row.col.f32.bf16.bf16.f32 "
        "{%0,%1,%2,%3}, {%4,%5,%6,%7}, {%8,%9}, {%0,%1,%2,%3};"
        : "+f"(c[0]), "+f"(c[1]), "+f"(c[2]), "+f"(c[3])
        : "r"(a[0]), "r"(a[1]), "r"(a[2]), "r"(a[3]), "r"(b0), "r"(b1));
}

// ---------------------------------------------------------------------------
// Kernel 0: split fp32 weights into bf16 hi/lo once (Wih f/b + Whh_f)
// ---------------------------------------------------------------------------
__global__ void conv_w_kernel(const float* __restrict__ Wf,
                              const float* __restrict__ Wb,
                              const float* __restrict__ Whh) {
    int i = blockIdx.x * blockDim.x + threadIdx.x;
    if (i < GG * FF) {
        float x = Wf[i];
        __nv_bfloat16 h = __float2bfloat16(x);
        g_Wh[0][i] = h;
        g_Wl[0][i] = __float2bfloat16(x - __bfloat162float(h));
        x = Wb[i];
        h = __float2bfloat16(x);
        g_Wh[1][i] = h;
        g_Wl[1][i] = __float2bfloat16(x - __bfloat162float(h));
    }
    if (i < GG * HH) {
        float x = Whh[i];
        __nv_bfloat16 h = __float2bfloat16(x);
        g_Whh_h[i] = h;
        g_Whh_l[i] = __float2bfloat16(x - __bfloat162float(h));
    }
}

// ---------------------------------------------------------------------------
// Kernel 1: gathered projection GEMM on HMMA (bf16 hi/lo split, fp32 acc)
// (unchanged from R12 — known good)
// ---------------------------------------------------------------------------
#define RSU 68                         // row stride in u32 (64 data + 4 pad)
#define AH_OFF 0
#define AL_OFF (128 * RSU)
#define BH_OFF (2 * 128 * RSU)
#define BL_OFF (2 * 128 * RSU + 256 * RSU)
#define PROJ_SMEM ((2 * 128 * RSU + 2 * 256 * RSU) * 4)   // 208896 B

__global__ __launch_bounds__(512, 1) void proj_mma_kernel(
    const int*   __restrict__ neigh,
    const float* __restrict__ table,
    const float* __restrict__ bih,
    const float* __restrict__ bhh,
    int M, int bwd)
{
    extern __shared__ uint32_t smu[];
    uint32_t* AH = smu + AH_OFF;
    uint32_t* AL = smu + AL_OFF;
    uint32_t* BH = smu + BH_OFF;
    uint32_t* BL = smu + BL_OFF;

    const int tid  = threadIdx.x;
    const int row0 = blockIdx.x * 128;
    float* outp = bwd ? g_xgb : g_xg;

    // ---- A: gather 128 rows, split fp32 -> bf16 hi/lo (4 threads / row) ----
    {
        const int r_l = tid >> 2;          // local row 0..127
        const int q   = tid & 3;           // quarter: cols [32q, 32q+32)
        int r = row0 + r_l; if (r >= M) r = M - 1;
        const int e = bwd ? neigh[r * KK + (KK - 1)] : neigh[r];
        const float4* src = (const float4*)(table + (size_t)e * FF) + q * 8;
        uint32_t* ah = AH + r_l * RSU + q * 16;
        uint32_t* al = AL + r_l * RSU + q * 16;
        #pragma unroll
        for (int j = 0; j < 8; j++) {
            float4 v = src[j];
            __nv_bfloat16 h0 = __float2bfloat16(v.x);
            __nv_bfloat16 h1 = __float2bfloat16(v.y);
            __nv_bfloat16 h2 = __float2bfloat16(v.z);
            __nv_bfloat16 h3 = __float2bfloat16(v.w);
            __nv_bfloat16 l0 = __float2bfloat16(v.x - __bfloat162float(h0));
            __nv_bfloat16 l1 = __float2bfloat16(v.y - __bfloat162float(h1));
            __nv_bfloat16 l2 = __float2bfloat16(v.z - __bfloat162float(h2));
            __nv_bfloat16 l3 = __float2bfloat16(v.w - __bfloat162float(h3));
            ah[j * 2 + 0] = pack2bf(h0, h1);
            ah[j * 2 + 1] = pack2bf(h2, h3);
            al[j * 2 + 0] = pack2bf(l0, l1);
            al[j * 2 + 1] = pack2bf(l2, l3);
        }
    }

    // ---- B: pre-split bf16 weights -> SMEM (2 threads / gate row) ----
    {
        const int row  = tid >> 1;         // gate 0..255
        const int half = tid & 1;          // cols [64h, 64h+64)
        const uint4* wh = (const uint4*)(g_Wh[bwd] + row * FF) + half * 8;
        const uint4* wl = (const uint4*)(g_Wl[bwd] + row * FF) + half * 8;
        uint32_t* bh = BH + row * RSU + half * 32;
        uint32_t* bl = BL + row * RSU + half * 32;
        #pragma unroll
        for (int j = 0; j < 8; j++) {
            uint4 vh = wh[j], vl = wl[j];
            bh[j * 4 + 0] = vh.x; bh[j * 4 + 1] = vh.y;
            bh[j * 4 + 2] = vh.z; bh[j * 4 + 3] = vh.w;
            bl[j * 4 + 0] = vl.x; bl[j * 4 + 1] = vl.y;
            bl[j * 4 + 2] = vl.z; bl[j * 4 + 3] = vl.w;
        }
    }
    __syncthreads();

    // ---- MMA mainloop ----
    const int w  = tid >> 5;
    const int l  = tid & 31;
    const int wm = w & 3;                  // m-tile (32 rows each)
    const int wn = w >> 2;                 // n-tile (64 cols each)
    const int lr = l >> 2, lc = l & 3;

    float acc[2][8][4];
    #pragma unroll
    for (int mi = 0; mi < 2; mi++)
        #pragma unroll
        for (int ni = 0; ni < 8; ni++)
            #pragma unroll
            for (int i = 0; i < 4; i++) acc[mi][ni][i] = 0.f;

    #pragma unroll
    for (int t = 0; t < 3; t++) {
        const uint32_t* Ab = (t == 1) ? AL : AH;
        const uint32_t* Bb = (t == 2) ? BL : BH;
        #pragma unroll
        for (int ks = 0; ks < 8; ks++) {
            const int kb = ks * 8;         // u32 col base within row
            uint32_t a[2][4];
            #pragma unroll
            for (int mi = 0; mi < 2; mi++) {
                const int br = wm * 32 + mi * 16 + lr;
                a[mi][0] = Ab[(br    ) * RSU + kb     + lc];
                a[mi][1] = Ab[(br + 8) * RSU + kb     + lc];
                a[mi][2] = Ab[(br    ) * RSU + kb + 4 + lc];
                a[mi][3] = Ab[(br + 8) * RSU + kb + 4 + lc];
            }
            #pragma unroll
            for (int ni = 0; ni < 8; ni++) {
                const int n = wn * 64 + ni * 8 + lr;
                uint32_t b0 = Bb[n * RSU + kb + lc];
                uint32_t b1 = Bb[n * RSU + kb + 4 + lc];
                mma16816(acc[0][ni], a[0], b0, b1);
                mma16816(acc[1][ni], a[1], b0, b1);
            }
        }
    }

    // ---- epilogue: +bias, store float2 pairs ----
    float2 bb[8];
    #pragma unroll
    for (int ni = 0; ni < 8; ni++) {
        int c = wn * 64 + ni * 8 + lc * 2;
        bb[ni].x = bih[c] + bhh[c];
        bb[ni].y = bih[c + 1] + bhh[c + 1];
    }
    #pragma unroll
    for (int mi = 0; mi < 2; mi++) {
        const int r = row0 + wm * 32 + mi * 16 + lr;
        #pragma unroll
        for (int ni = 0; ni < 8; ni++) {
            const int c = wn * 64 + ni * 8 + lc * 2;
            if (r < M) {
                float2 v0 = make_float2(acc[mi][ni][0] + bb[ni].x,
                                        acc[mi][ni][1] + bb[ni].y);
                *(float2*)(outp + (size_t)r * GG + c) = v0;
            }
            if (r + 8 < M) {
                float2 v1 = make_float2(acc[mi][ni][2] + bb[ni].x,
                                        acc[mi][ni][3] + bb[ni].y);
                *(float2*)(outp + (size_t)(r + 8) * GG + c) = v1;
            }
        }
    }
}

// ---------------------------------------------------------------------------
// Kernel 2: forward LSTM recurrence on HMMA + backward single-cell epilogue
// CTA = 64 nodes, 256 threads (8 warps). Per step:
//   acc init <- g_xg fragments (global f32)
//   acc += h_prev[64x64] @ Whh[256x64]^T   (3-pass bf16 hi/lo HMMA)
//   gates -> SMEM; per-thread c/h update; h split hi/lo -> SMEM for next step
// SMEM u32 layout:
//   WH [256][36], WL [256][36]   (Whh hi/lo, k-contiguous, n=gate rows)
//   HHs[64][36],  HLs[64][36]    (h_prev hi/lo, k=hidden contiguous)
//   GT [64][260] f32             (pre-activation gates)
// ---------------------------------------------------------------------------
#define LW  36                    // row stride u32 for W/h tiles (32 data + 4)
#define GTS 260                   // gate buffer row stride (f32)
#define WH_OFF  0
#define WL_OFF  (256 * LW)
#define HH_OFF  (2 * 256 * LW)
#define HL_OFF  (2 * 256 * LW + 64 * LW)
#define GT_OFF  (2 * 256 * LW + 2 * 64 * LW)
#define LSTM_SMEM ((GT_OFF + 64 * GTS) * 4)   // 158720 B

__global__ __launch_bounds__(256, 1) void lstm_mma_kernel(float* __restrict__ out)
{
    extern __shared__ uint32_t su[];
    uint32_t* WH  = su + WH_OFF;
    uint32_t* WL  = su + WL_OFF;
    uint32_t* HHs = su + HH_OFF;
    uint32_t* HLs = su + HL_OFF;
    float*    GT  = (float*)(su + GT_OFF);

    const int tid   = threadIdx.x;
    const int w     = tid >> 5;
    const int l     = tid & 31;
    const int wm    = w & 1;               // 2 m-tiles of 32 rows
    const int wn    = w >> 1;              // 4 n-tiles of 64 gates
    const int lr    = l >> 2, lc = l & 3;
    const int node0 = blockIdx.x * 64;

    // load pre-split Whh into SMEM (u32 = 2 bf16, k-contiguous rows of 32 u32)
    {
        const uint32_t* wh = (const uint32_t*)g_Whh_h;
        const uint32_t* wl = (const uint32_t*)g_Whh_l;
        for (int i = tid; i < GG * 32; i += 256) {
            int g = i >> 5, c = i & 31;
            WH[g * LW + c] = wh[i];
            WL[g * LW + c] = wl[i];
        }
    }
    __syncthreads();

    // cell state: thread owns node (tid>>2), hidden units (tid&3)*16 .. +15
    const int nloc = tid >> 2;
    const int hb   = (tid & 3) * 16;
    const int nmy  = node0 + nloc;
    float cst[16];
    #pragma unroll
    for (int i = 0; i < 16; i++) cst[i] = 0.f;

    // global node rows for xg fragment loads (clamped)
    int nrow[2][2];
    #pragma unroll
    for (int mi = 0; mi < 2; mi++) {
        int base = node0 + wm * 32 + mi * 16 + lr;
        nrow[mi][0] = base < NN ? base : NN - 1;
        nrow[mi][1] = base + 8 < NN ? base + 8 : NN - 1;
    }

    for (int k = 0; k < KK; k++) {
        // ---- acc init from g_xg (includes both biases) ----
        float acc[2][8][4];
        #pragma unroll
        for (int mi = 0; mi < 2; mi++)
            #pragma unroll
            for (int half = 0; half < 2; half++) {
                const float* src = g_xg + ((size_t)nrow[mi][half] * KK + k) * GG
                                 + wn * 64 + lc * 2;
                #pragma unroll
                for (int ni = 0; ni < 8; ni++) {
                    float2 v = *(const float2*)(src + ni * 8);
                    acc[mi][ni][half * 2 + 0] = v.x;
                    acc[mi][ni][half * 2 + 1] = v.y;
                }
            }

        // ---- += h_prev @ Whh^T (3-pass bf16 hi/lo), skip k=0 (h=0) ----
        if (k > 0) {
            #pragma unroll
            for (int t = 0; t < 3; t++) {
                const uint32_t* Ab = (t == 1) ? HLs : HHs;
                const uint32_t* Bb = (t == 2) ? WL : WH;
                #pragma unroll
                for (int s = 0; s < 4; s++) {
                    const int kb = s * 8;
                    uint32_t a[2][4];
                    #pragma unroll
                    for (int mi = 0; mi < 2; mi++) {
                        const int br = wm * 32 + mi * 16 + lr;
                        a[mi][0] = Ab[(br    ) * LW + kb     + lc];
                        a[mi][1] = Ab[(br + 8) * LW + kb     + lc];
                        a[mi][2] = Ab[(br    ) * LW + kb + 4 + lc];
                        a[mi][3] = Ab[(br + 8) * LW + kb + 4 + lc];
                    }
                    #pragma unroll
                    for (int ni = 0; ni < 8; ni++) {
                        const int n = wn * 64 + ni * 8 + lr;
                        uint32_t b0 = Bb[n * LW + kb + lc];
                        uint32_t b1 = Bb[n * LW + kb + 4 + lc];
                        mma16816(acc[0][ni], a[0], b0, b1);
                        mma16816(acc[1][ni], a[1], b0, b1);
                    }
                }
            }
            __syncthreads();   // h_prev reads done before c-update overwrites
        }

        // ---- gates -> SMEM ----
        #pragma unroll
        for (int mi = 0; mi < 2; mi++) {
            const int row = wm * 32 + mi * 16 + lr;
            #pragma unroll
            for (int ni = 0; ni < 8; ni++) {
                const int col = wn * 64 + ni * 8 + lc * 2;
                *(float2*)&GT[(row    ) * GTS + col] =
                    make_float2(acc[mi][ni][0], acc[mi][ni][1]);
                *(float2*)&GT[(row + 8) * GTS + col] =
                    make_float2(acc[mi][ni][2], acc[mi][ni][3]);
            }
        }
        __syncthreads();

        // ---- c/h update (thread owns 16 (node,h) cells) ----
        const float* gr = &GT[nloc * GTS];
        uint32_t* hhd = &HHs[nloc * LW + (tid & 3) * 8];
        uint32_t* hld = &HLs[nloc * LW + (tid & 3) * 8];
        float hout[16];
        #pragma unroll
        for (int j4 = 0; j4 < 4; j4++) {
            float4 gi = *(const float4*)&gr[      hb + j4 * 4];
            float4 gf = *(const float4*)&gr[ 64 + hb + j4 * 4];
            float4 gg = *(const float4*)&gr[128 + hb + j4 * 4];
            float4 go = *(const float4*)&gr[192 + hb + j4 * 4];
            const float iv[4] = {gi.x, gi.y, gi.z, gi.w};
            const float fv[4] = {gf.x, gf.y, gf.z, gf.w};
            const float gv[4] = {gg.x, gg.y, gg.z, gg.w};
            const float ov[4] = {go.x, go.y, go.z, go.w};
            #pragma unroll
            for (int e = 0; e < 4; e++) {
                int idx = j4 * 4 + e;
                float ig = sigf(iv[e]);
                float fg = sigf(fv[e]);
                float gz = tanh_fast(gv[e]);
                float og = sigf(ov[e]);
                cst[idx] = fg * cst[idx] + ig * gz;
                hout[idx] = og * tanh_fast(cst[idx]);
            }
            // split h -> bf16 hi/lo, pack pairs
            #pragma unroll
            for (int p = 0; p < 2; p++) {
                float x = hout[j4 * 4 + p * 2], y = hout[j4 * 4 + p * 2 + 1];
                __nv_bfloat16 xh = __float2bfloat16(x);
                __nv_bfloat16 yh = __float2bfloat16(y);
                __nv_bfloat16 xl = __float2bfloat16(x - __bfloat162float(xh));
                __nv_bfloat16 yl = __float2bfloat16(y - __bfloat162float(yh));
                hhd[j4 * 2 + p] = pack2bf(xh, yh);
                hld[j4 * 2 + p] = pack2bf(xl, yl);
            }
        }
        __syncthreads();   // new h visible before next step's MMA

        if (k == KK - 1 && nmy < NN) {
            #pragma unroll
            for (int i = 0; i < 16; i++)
                out[(size_t)nmy * (2 * HH) + hb + i] = hout[i];
        }
    }

    // ---- backward direction: single cell on x[:, K-1] -> out[n][64:128] ----
    for (int i = tid; i < 64 * HH; i += 256) {
        int nn = i >> 6, hh2 = i & 63;
        int n = node0 + nn;
        if (n < NN) {
            const float* s = g_xgb + (size_t)n * GG;
            float ig = sigf(s[hh2]);
            float gz = tanh_fast(s[128 + hh2]);
            float og = sigf(s[192 + hh2]);
            float cc = ig * gz;
            out[(size_t)n * (2 * HH) + HH + hh2] = og * tanh_fast(cc);
        }
    }
}

// ---------------------------------------------------------------------------
// Launch. Input order per metadata:
// 0 neigh_idx[N,K] i32, 1 embed_table[V,F] f32,
// 2 Wih_f[256,128], 3 Whh_f[256,64], 4 bih_f[256], 5 bhh_f[256],
// 6 Wih_b[256,128], 7 Whh_b[256,64], 8 bih_b[256], 9 bhh_b[256]
// out: [N, 128] f32
// ---------------------------------------------------------------------------
extern "C" void kernel_launch(void* const* d_in, const int* in_sizes, int n_in,
                              void* d_out, int out_size)
{
    const int*   neigh  = (const int*)  d_in[0];
    const float* table  = (const float*)d_in[1];
    const float* Wih_f  = (const float*)d_in[2];
    const float* Whh_f  = (const float*)d_in[3];
    const float* bih_f  = (const float*)d_in[4];
    const float* bhh_f  = (const float*)d_in[5];
    const float* Wih_b  = (const float*)d_in[6];
    const float* bih_b  = (const float*)d_in[8];
    const float* bhh_b  = (const float*)d_in[9];
    float* out = (float*)d_out;

    (void)in_sizes; (void)n_in; (void)out_size;

    // 0) split weights into bf16 hi/lo (Wih f/b + Whh_f)
    conv_w_kernel<<<128, 256>>>(Wih_f, Wih_b, Whh_f);

    // 1) HMMA gathered projections
    cudaFuncSetAttribute(proj_mma_kernel,
                         cudaFuncAttributeMaxDynamicSharedMemorySize, PROJ_SMEM);
    proj_mma_kernel<<<(MF + 127) / 128, 512, PROJ_SMEM>>>(neigh, table, bih_f, bhh_f, MF, 0);
    proj_mma_kernel<<<(NN + 127) / 128, 512, PROJ_SMEM>>>(neigh, table, bih_b, bhh_b, NN, 1);

    // 2) HMMA recurrence + output assembly
    cudaFuncSetAttribute(lstm_mma_kernel,
                         cudaFuncAttributeMaxDynamicSharedMemorySize, LSTM_SMEM);
    lstm_mma_kernel<<<(NN + 63) / 64, 256, LSTM_SMEM>>>(out);
}

// round 14
// speedup vs baseline: 1.1638x; 1.1638x over previous
#include <cuda_runtime.h>
#include <cuda_bf16.h>
#include <math.h>
#include <stdint.h>

// Problem dims (fixed by the dataset)
#define NN 50000   // nodes
#define KK 10      // sampled neighbors (sequence length)
#define FF 128     // input_dim
#define HH 64      // hidden per direction
#define GG 256     // 4*H gates
#define MF (NN*KK) // 500000 projection rows (forward)

// Scratch (device globals — no allocation allowed)
__device__ float g_xg [(size_t)MF * GG];  // [N*K, 256] forward input projections (+bias)
__device__ float g_xgb[(size_t)NN * GG];  // [N, 256]   backward-last-step projections (+bias)
// bf16 hi/lo split weight copies: [0]=forward Wih, [1]=backward Wih
__device__ __nv_bfloat16 g_Wh[2][GG * FF];
__device__ __nv_bfloat16 g_Wl[2][GG * FF];
// bf16 hi/lo split of Whh_f [256][64]
__device__ __nv_bfloat16 g_Whh_h[GG * HH];
__device__ __nv_bfloat16 g_Whh_l[GG * HH];

__device__ __forceinline__ float sigf(float x) {
    return 1.f / (1.f + __expf(-x));
}
__device__ __forceinline__ float tanh_fast(float x) {
    float e = __expf(2.f * x);
    return 1.f - 2.f / (e + 1.f);
}
__device__ __forceinline__ uint32_t pack2bf(__nv_bfloat16 a, __nv_bfloat16 b) {
    return ((uint32_t)__bfloat16_as_ushort(b) << 16) | __bfloat16_as_ushort(a);
}

// warp-level bf16 HMMA (portable PTX, no sm_103a-only features)
__device__ __forceinline__ void mma16816(float* c, const uint32_t* a,
                                         uint32_t b0, uint32_t b1) {
    asm volatile(
        "mma.sync.aligned.m16n8k16.row.col.f32.bf16.bf16.f32 "
        "{%0,%1,%2,%3}, {%4,%5,%6,%7}, {%8,%9}, {%0,%1,%2,%3};"
        : "+f"(c[0]), "+f"(c[1]), "+f"(c[2]), "+f"(c[3])
        : "r"(a[0]), "r"(a[1]), "r"(a[2]), "r"(a[3]), "r"(b0), "r"(b1));
}

// ---------------------------------------------------------------------------
// Kernel 0: split fp32 weights into bf16 hi/lo once (Wih f/b + Whh_f)
// ---------------------------------------------------------------------------
__global__ void conv_w_kernel(const float* __restrict__ Wf,
                              const float* __restrict__ Wb,
                              const float* __restrict__ Whh) {
    int i = blockIdx.x * blockDim.x + threadIdx.x;
    if (i < GG * FF) {
        float x = Wf[i];
        __nv_bfloat16 h = __float2bfloat16(x);
        g_Wh[0][i] = h;
        g_Wl[0][i] = __float2bfloat16(x - __bfloat162float(h));
        x = Wb[i];
        h = __float2bfloat16(x);
        g_Wh[1][i] = h;
        g_Wl[1][i] = __float2bfloat16(x - __bfloat162float(h));
    }
    if (i < GG * HH) {
        float x = Whh[i];
        __nv_bfloat16 h = __float2bfloat16(x);
        g_Whh_h[i] = h;
        g_Whh_l[i] = __float2bfloat16(x - __bfloat162float(h));
    }
}

// ---------------------------------------------------------------------------
// Kernel 1: gathered projection GEMM on HMMA (bf16 hi/lo split, fp32 acc)
// (unchanged from R12 — known good)
// ---------------------------------------------------------------------------
#define RSU 68                         // row stride in u32 (64 data + 4 pad)
#define AH_OFF 0
#define AL_OFF (128 * RSU)
#define BH_OFF (2 * 128 * RSU)
#define BL_OFF (2 * 128 * RSU + 256 * RSU)
#define PROJ_SMEM ((2 * 128 * RSU + 2 * 256 * RSU) * 4)   // 208896 B

__global__ __launch_bounds__(512, 1) void proj_mma_kernel(
    const int*   __restrict__ neigh,
    const float* __restrict__ table,
    const float* __restrict__ bih,
    const float* __restrict__ bhh,
    int M, int bwd)
{
    extern __shared__ uint32_t smu[];
    uint32_t* AH = smu + AH_OFF;
    uint32_t* AL = smu + AL_OFF;
    uint32_t* BH = smu + BH_OFF;
    uint32_t* BL = smu + BL_OFF;

    const int tid  = threadIdx.x;
    const int row0 = blockIdx.x * 128;
    float* outp = bwd ? g_xgb : g_xg;

    // ---- A: gather 128 rows, split fp32 -> bf16 hi/lo (4 threads / row) ----
    {
        const int r_l = tid >> 2;          // local row 0..127
        const int q   = tid & 3;           // quarter: cols [32q, 32q+32)
        int r = row0 + r_l; if (r >= M) r = M - 1;
        const int e = bwd ? neigh[r * KK + (KK - 1)] : neigh[r];
        const float4* src = (const float4*)(table + (size_t)e * FF) + q * 8;
        uint32_t* ah = AH + r_l * RSU + q * 16;
        uint32_t* al = AL + r_l * RSU + q * 16;
        #pragma unroll
        for (int j = 0; j < 8; j++) {
            float4 v = src[j];
            __nv_bfloat16 h0 = __float2bfloat16(v.x);
            __nv_bfloat16 h1 = __float2bfloat16(v.y);
            __nv_bfloat16 h2 = __float2bfloat16(v.z);
            __nv_bfloat16 h3 = __float2bfloat16(v.w);
            __nv_bfloat16 l0 = __float2bfloat16(v.x - __bfloat162float(h0));
            __nv_bfloat16 l1 = __float2bfloat16(v.y - __bfloat162float(h1));
            __nv_bfloat16 l2 = __float2bfloat16(v.z - __bfloat162float(h2));
            __nv_bfloat16 l3 = __float2bfloat16(v.w - __bfloat162float(h3));
            ah[j * 2 + 0] = pack2bf(h0, h1);
            ah[j * 2 + 1] = pack2bf(h2, h3);
            al[j * 2 + 0] = pack2bf(l0, l1);
            al[j * 2 + 1] = pack2bf(l2, l3);
        }
    }

    // ---- B: pre-split bf16 weights -> SMEM (2 threads / gate row) ----
    {
        const int row  = tid >> 1;         // gate 0..255
        const int half = tid & 1;          // cols [64h, 64h+64)
        const uint4* wh = (const uint4*)(g_Wh[bwd] + row * FF) + half * 8;
        const uint4* wl = (const uint4*)(g_Wl[bwd] + row * FF) + half * 8;
        uint32_t* bh = BH + row * RSU + half * 32;
        uint32_t* bl = BL + row * RSU + half * 32;
        #pragma unroll
        for (int j = 0; j < 8; j++) {
            uint4 vh = wh[j], vl = wl[j];
            bh[j * 4 + 0] = vh.x; bh[j * 4 + 1] = vh.y;
            bh[j * 4 + 2] = vh.z; bh[j * 4 + 3] = vh.w;
            bl[j * 4 + 0] = vl.x; bl[j * 4 + 1] = vl.y;
            bl[j * 4 + 2] = vl.z; bl[j * 4 + 3] = vl.w;
        }
    }
    __syncthreads();

    // ---- MMA mainloop ----
    const int w  = tid >> 5;
    const int l  = tid & 31;
    const int wm = w & 3;                  // m-tile (32 rows each)
    const int wn = w >> 2;                 // n-tile (64 cols each)
    const int lr = l >> 2, lc = l & 3;

    float acc[2][8][4];
    #pragma unroll
    for (int mi = 0; mi < 2; mi++)
        #pragma unroll
        for (int ni = 0; ni < 8; ni++)
            #pragma unroll
            for (int i = 0; i < 4; i++) acc[mi][ni][i] = 0.f;

    #pragma unroll
    for (int t = 0; t < 3; t++) {
        const uint32_t* Ab = (t == 1) ? AL : AH;
        const uint32_t* Bb = (t == 2) ? BL : BH;
        #pragma unroll
        for (int ks = 0; ks < 8; ks++) {
            const int kb = ks * 8;         // u32 col base within row
            uint32_t a[2][4];
            #pragma unroll
            for (int mi = 0; mi < 2; mi++) {
                const int br = wm * 32 + mi * 16 + lr;
                a[mi][0] = Ab[(br    ) * RSU + kb     + lc];
                a[mi][1] = Ab[(br + 8) * RSU + kb     + lc];
                a[mi][2] = Ab[(br    ) * RSU + kb + 4 + lc];
                a[mi][3] = Ab[(br + 8) * RSU + kb + 4 + lc];
            }
            #pragma unroll
            for (int ni = 0; ni < 8; ni++) {
                const int n = wn * 64 + ni * 8 + lr;
                uint32_t b0 = Bb[n * RSU + kb + lc];
                uint32_t b1 = Bb[n * RSU + kb + 4 + lc];
                mma16816(acc[0][ni], a[0], b0, b1);
                mma16816(acc[1][ni], a[1], b0, b1);
            }
        }
    }

    // ---- epilogue: +bias, store float2 pairs ----
    float2 bb[8];
    #pragma unroll
    for (int ni = 0; ni < 8; ni++) {
        int c = wn * 64 + ni * 8 + lc * 2;
        bb[ni].x = bih[c] + bhh[c];
        bb[ni].y = bih[c + 1] + bhh[c + 1];
    }
    #pragma unroll
    for (int mi = 0; mi < 2; mi++) {
        const int r = row0 + wm * 32 + mi * 16 + lr;
        #pragma unroll
        for (int ni = 0; ni < 8; ni++) {
            const int c = wn * 64 + ni * 8 + lc * 2;
            if (r < M) {
                float2 v0 = make_float2(acc[mi][ni][0] + bb[ni].x,
                                        acc[mi][ni][1] + bb[ni].y);
                *(float2*)(outp + (size_t)r * GG + c) = v0;
            }
            if (r + 8 < M) {
                float2 v1 = make_float2(acc[mi][ni][2] + bb[ni].x,
                                        acc[mi][ni][3] + bb[ni].y);
                *(float2*)(outp + (size_t)(r + 8) * GG + c) = v1;
            }
        }
    }
}

// ---------------------------------------------------------------------------
// Kernel 2: forward LSTM recurrence on HMMA, register-resident gates
// CTA = 64 nodes, 512 threads (16 warps). Warp (wm = w&3) owns rows
// [16wm,16wm+16); warp (wn = w>>2) owns hidden cols j in {8wn..8wn+7} u
// {32+8wn..+7} ACROSS ALL FOUR gate quarters (ni = 2q+jg -> col
// q*64 + jg*32 + wn*8). So after the MMA each thread holds i/f/g/o for its
// (node, j) cells in registers -> c/h update with no gate SMEM round-trip.
// h ping-pongs between two SMEM buffers: step k reads HB[k&1], writes
// HB[(k+1)&1] -> exactly ONE __syncthreads per step.
// SMEM u32: WH[256][36], WL[256][36], HB[2]{hi[64][36], lo[64][36]}
// ---------------------------------------------------------------------------
#define LW  36
#define WHO 0
#define WLO (256 * LW)                 // 9216
#define HBO (2 * 256 * LW)             // 18432
#define HBSTRIDE (2 * 64 * LW)         // 4608 u32 per ping-pong buffer (hi+lo)
#define LSTM_SMEM ((HBO + 2 * HBSTRIDE) * 4)   // 110592 B

__global__ __launch_bounds__(512, 1) void lstm_mma_kernel(float* __restrict__ out)
{
    extern __shared__ uint32_t su[];
    uint32_t* WH = su + WHO;
    uint32_t* WL = su + WLO;

    const int tid   = threadIdx.x;
    const int w     = tid >> 5;
    const int l     = tid & 31;
    const int wm    = w & 3;               // row tile: 16 rows
    const int wn    = w >> 2;              // j-octet selector
    const int lr    = l >> 2, lc = l & 3;
    const int node0 = blockIdx.x * 64;

    // load pre-split Whh (k-contiguous u32 rows of 32)
    {
        const uint32_t* wh = (const uint32_t*)g_Whh_h;
        const uint32_t* wl = (const uint32_t*)g_Whh_l;
        for (int i = tid; i < GG * 32; i += 512) {
            int g = i >> 5, c = i & 31;
            WH[g * LW + c] = wh[i];
            WL[g * LW + c] = wl[i];
        }
    }
    __syncthreads();

    // this thread's rows (local + clamped global)
    const int rloc0 = wm * 16 + lr;        // hf=0 row, local
    int nrow[2];
    #pragma unroll
    for (int hf = 0; hf < 2; hf++) {
        int n = node0 + rloc0 + hf * 8;
        nrow[hf] = n < NN ? n : NN - 1;
    }

    // cell state: cst[hf*4 + jg*2 + e]
    float cst[8];
    #pragma unroll
    for (int i = 0; i < 8; i++) cst[i] = 0.f;
    float hout[8];

    for (int k = 0; k < KK; k++) {
        // ---- acc init from g_xg (includes both biases) ----
        float acc[8][4];
        #pragma unroll
        for (int hf = 0; hf < 2; hf++) {
            const float* src = g_xg + ((size_t)nrow[hf] * KK + k) * GG
                             + wn * 8 + lc * 2;
            #pragma unroll
            for (int ni = 0; ni < 8; ni++) {
                const int q = ni >> 1, jg = ni & 1;
                float2 v = *(const float2*)(src + q * 64 + jg * 32);
                acc[ni][hf * 2 + 0] = v.x;
                acc[ni][hf * 2 + 1] = v.y;
            }
        }

        // ---- += h_prev @ Whh^T (3-pass bf16 hi/lo), skip k=0 ----
        if (k > 0) {
            const uint32_t* HHp = su + HBO + (k & 1) * HBSTRIDE;
            const uint32_t* HLp = HHp + 64 * LW;
            #pragma unroll
            for (int t = 0; t < 3; t++) {
                const uint32_t* Ab = (t == 1) ? HLp : HHp;
                const uint32_t* Bb = (t == 2) ? WL : WH;
                #pragma unroll
                for (int s = 0; s < 4; s++) {
                    const int kb = s * 8;
                    uint32_t a[4];
                    a[0] = Ab[(rloc0    ) * LW + kb     + lc];
                    a[1] = Ab[(rloc0 + 8) * LW + kb     + lc];
                    a[2] = Ab[(rloc0    ) * LW + kb + 4 + lc];
                    a[3] = Ab[(rloc0 + 8) * LW + kb + 4 + lc];
                    #pragma unroll
                    for (int ni = 0; ni < 8; ni++) {
                        const int q = ni >> 1, jg = ni & 1;
                        const int n = q * 64 + jg * 32 + wn * 8 + lr;
                        uint32_t b0 = Bb[n * LW + kb + lc];
                        uint32_t b1 = Bb[n * LW + kb + 4 + lc];
                        mma16816(acc[ni], a, b0, b1);
                    }
                }
            }
        }

        // ---- c/h update entirely in registers; write h to next buffer ----
        uint32_t* HHn = su + HBO + ((k + 1) & 1) * HBSTRIDE;
        uint32_t* HLn = HHn + 64 * LW;
        #pragma unroll
        for (int hf = 0; hf < 2; hf++) {
            #pragma unroll
            for (int jg = 0; jg < 2; jg++) {
                #pragma unroll
                for (int e = 0; e < 2; e++) {
                    const int idx = hf * 4 + jg * 2 + e;
                    float ig = sigf(acc[0 + jg][hf * 2 + e]);
                    float fg = sigf(acc[2 + jg][hf * 2 + e]);
                    float gz = tanh_fast(acc[4 + jg][hf * 2 + e]);
                    float og = sigf(acc[6 + jg][hf * 2 + e]);
                    cst[idx] = fg * cst[idx] + ig * gz;
                    hout[idx] = og * tanh_fast(cst[idx]);
                }
                float x = hout[hf * 4 + jg * 2], y = hout[hf * 4 + jg * 2 + 1];
                __nv_bfloat16 xh = __float2bfloat16(x);
                __nv_bfloat16 yh = __float2bfloat16(y);
                __nv_bfloat16 xl = __float2bfloat16(x - __bfloat162float(xh));
                __nv_bfloat16 yl = __float2bfloat16(y - __bfloat162float(yh));
                const int a = (rloc0 + hf * 8) * LW + wn * 4 + jg * 16 + lc;
                HHn[a] = pack2bf(xh, yh);
                HLn[a] = pack2bf(xl, yl);
            }
        }
        __syncthreads();   // new h visible before next step's MMA reads

        if (k == KK - 1) {
            #pragma unroll
            for (int hf = 0; hf < 2; hf++) {
                const int n = node0 + rloc0 + hf * 8;
                if (n < NN) {
                    #pragma unroll
                    for (int jg = 0; jg < 2; jg++) {
                        const int j = wn * 8 + jg * 32 + lc * 2;
                        *(float2*)(out + (size_t)n * (2 * HH) + j) =
                            make_float2(hout[hf * 4 + jg * 2],
                                        hout[hf * 4 + jg * 2 + 1]);
                    }
                }
            }
        }
    }

    // ---- backward direction: single cell on x[:, K-1] -> out[n][64:128] ----
    for (int i = tid; i < 64 * HH; i += 512) {
        int nn = i >> 6, hh2 = i & 63;
        int n = node0 + nn;
        if (n < NN) {
            const float* s = g_xgb + (size_t)n * GG;
            float ig = sigf(s[hh2]);
            float gz = tanh_fast(s[128 + hh2]);
            float og = sigf(s[192 + hh2]);
            float cc = ig * gz;
            out[(size_t)n * (2 * HH) + HH + hh2] = og * tanh_fast(cc);
        }
    }
}

// ---------------------------------------------------------------------------
// Launch. Input order per metadata:
// 0 neigh_idx[N,K] i32, 1 embed_table[V,F] f32,
// 2 Wih_f[256,128], 3 Whh_f[256,64], 4 bih_f[256], 5 bhh_f[256],
// 6 Wih_b[256,128], 7 Whh_b[256,64], 8 bih_b[256], 9 bhh_b[256]
// out: [N, 128] f32
// ---------------------------------------------------------------------------
extern "C" void kernel_launch(void* const* d_in, const int* in_sizes, int n_in,
                              void* d_out, int out_size)
{
    const int*   neigh  = (const int*)  d_in[0];
    const float* table  = (const float*)d_in[1];
    const float* Wih_f  = (const float*)d_in[2];
    const float* Whh_f  = (const float*)d_in[3];
    const float* bih_f  = (const float*)d_in[4];
    const float* bhh_f  = (const float*)d_in[5];
    const float* Wih_b  = (const float*)d_in[6];
    const float* bih_b  = (const float*)d_in[8];
    const float* bhh_b  = (const float*)d_in[9];
    float* out = (float*)d_out;

    (void)in_sizes; (void)n_in; (void)out_size;

    // 0) split weights into bf16 hi/lo (Wih f/b + Whh_f)
    conv_w_kernel<<<128, 256>>>(Wih_f, Wih_b, Whh_f);

    // 1) HMMA gathered projections
    cudaFuncSetAttribute(proj_mma_kernel,
                         cudaFuncAttributeMaxDynamicSharedMemorySize, PROJ_SMEM);
    proj_mma_kernel<<<(MF + 127) / 128, 512, PROJ_SMEM>>>(neigh, table, bih_f, bhh_f, MF, 0);
    proj_mma_kernel<<<(NN + 127) / 128, 512, PROJ_SMEM>>>(neigh, table, bih_b, bhh_b, NN, 1);

    // 2) HMMA recurrence + output assembly (register-resident gates)
    cudaFuncSetAttribute(lstm_mma_kernel,
                         cudaFuncAttributeMaxDynamicSharedMemorySize, LSTM_SMEM);
    lstm_mma_kernel<<<(NN + 63) / 64, 512, LSTM_SMEM>>>(out);
}

// round 16
// speedup vs baseline: 1.4602x; 1.2547x over previous
#include <cuda_runtime.h>
#include <cuda_bf16.h>
#include <math.h>
#include <stdint.h>

// Problem dims (fixed by the dataset)
#define NN 50000   // nodes
#define KK 10      // sampled neighbors (sequence length)
#define FF 128     // input_dim
#define HH 64      // hidden per direction
#define GG 256     // 4*H gates
#define MF (NN*KK) // 500000 projection rows (forward)

// Scratch (device globals — no allocation allowed)
__device__ float g_xg [(size_t)MF * GG];  // [N*K, 256] forward input projections (+bias)
__device__ float g_xgb[(size_t)NN * GG];  // [N, 256]   backward-last-step projections (+bias)
// bf16 hi/lo split weight copies: [0]=forward Wih, [1]=backward Wih
__device__ __nv_bfloat16 g_Wh[2][GG * FF];
__device__ __nv_bfloat16 g_Wl[2][GG * FF];
// bf16 hi/lo split of Whh_f [256][64]
__device__ __nv_bfloat16 g_Whh_h[GG * HH];
__device__ __nv_bfloat16 g_Whh_l[GG * HH];

__device__ __forceinline__ float sigf(float x) {
    return 1.f / (1.f + __expf(-x));
}
__device__ __forceinline__ float tanh_fast(float x) {
    float e = __expf(2.f * x);
    return 1.f - 2.f / (e + 1.f);
}
__device__ __forceinline__ uint32_t pack2bf(__nv_bfloat16 a, __nv_bfloat16 b) {
    return ((uint32_t)__bfloat16_as_ushort(b) << 16) | __bfloat16_as_ushort(a);
}
__device__ __forceinline__ uint32_t smem_u32(const void* p) {
    uint32_t a;
    asm("{ .reg .u64 t; cvta.to.shared.u64 t, %1; cvt.u32.u64 %0, t; }"
        : "=r"(a) : "l"(p));
    return a;
}
__device__ __forceinline__ void cp_async16(uint32_t dst, const void* src) {
    asm volatile("cp.async.cg.shared.global [%0], [%1], 16;"
                 :: "r"(dst), "l"(src) : "memory");
}

// warp-level bf16 HMMA (portable PTX, no sm_103a-only features)
__device__ __forceinline__ void mma16816(float* c, const uint32_t* a,
                                         uint32_t b0, uint32_t b1) {
    asm volatile(
        "mma.sync.aligned.m16n8k16.row.col.f32.bf16.bf16.f32 "
        "{%0,%1,%2,%3}, {%4,%5,%6,%7}, {%8,%9}, {%0,%1,%2,%3};"
        : "+f"(c[0]), "+f"(c[1]), "+f"(c[2]), "+f"(c[3])
        : "r"(a[0]), "r"(a[1]), "r"(a[2]), "r"(a[3]), "r"(b0), "r"(b1));
}

// ---------------------------------------------------------------------------
// Kernel 0: split fp32 weights into bf16 hi/lo once (Wih f/b + Whh_f)
// ---------------------------------------------------------------------------
__global__ void conv_w_kernel(const float* __restrict__ Wf,
                              const float* __restrict__ Wb,
                              const float* __restrict__ Whh) {
    int i = blockIdx.x * blockDim.x + threadIdx.x;
    if (i < GG * FF) {
        float x = Wf[i];
        __nv_bfloat16 h = __float2bfloat16(x);
        g_Wh[0][i] = h;
        g_Wl[0][i] = __float2bfloat16(x - __bfloat162float(h));
        x = Wb[i];
        h = __float2bfloat16(x);
        g_Wh[1][i] = h;
        g_Wl[1][i] = __float2bfloat16(x - __bfloat162float(h));
    }
    if (i < GG * HH) {
        float x = Whh[i];
        __nv_bfloat16 h = __float2bfloat16(x);
        g_Whh_h[i] = h;
        g_Whh_l[i] = __float2bfloat16(x - __bfloat162float(h));
    }
}

// ---------------------------------------------------------------------------
// Kernel 1: gathered projection GEMM on HMMA (bf16 hi/lo split, fp32 acc)
// B streams via cp.async (issued first); A gather batches LDGs into regs
// (MLP=8) before converting -> load phase mostly overlapped.
// ---------------------------------------------------------------------------
#define RSU 68                         // row stride in u32 (64 data + 4 pad)
#define AH_OFF 0
#define AL_OFF (128 * RSU)
#define BH_OFF (2 * 128 * RSU)
#define BL_OFF (2 * 128 * RSU + 256 * RSU)
#define PROJ_SMEM ((2 * 128 * RSU + 2 * 256 * RSU) * 4)   // 208896 B

__global__ __launch_bounds__(512, 1) void proj_mma_kernel(
    const int*   __restrict__ neigh,
    const float* __restrict__ table,
    const float* __restrict__ bih,
    const float* __restrict__ bhh,
    int M, int bwd)
{
    extern __shared__ uint32_t smu[];
    uint32_t* AH = smu + AH_OFF;
    uint32_t* AL = smu + AL_OFF;
    const uint32_t sb = smem_u32(smu);

    const int tid  = threadIdx.x;
    const int row0 = blockIdx.x * 128;
    float* outp = bwd ? g_xgb : g_xg;

    // ---- B: pre-split bf16 weights -> SMEM via cp.async (issued first) ----
    {
        const int row  = tid >> 1;         // gate 0..255
        const int half = tid & 1;          // cols [64h, 64h+64)
        const char* wh = (const char*)(g_Wh[bwd] + row * FF) + half * 128;
        const char* wl = (const char*)(g_Wl[bwd] + row * FF) + half * 128;
        uint32_t bh = sb + (BH_OFF + row * RSU + half * 32) * 4;
        uint32_t bl = sb + (BL_OFF + row * RSU + half * 32) * 4;
        #pragma unroll
        for (int j = 0; j < 8; j++) {
            cp_async16(bh + j * 16, wh + j * 16);
            cp_async16(bl + j * 16, wl + j * 16);
        }
        asm volatile("cp.async.commit_group;" ::: "memory");
    }

    // ---- A: gather 128 rows (batched LDG), split fp32 -> bf16 hi/lo ----
    {
        const int r_l = tid >> 2;          // local row 0..127
        const int q   = tid & 3;           // quarter: cols [32q, 32q+32)
        int r = row0 + r_l; if (r >= M) r = M - 1;
        const int e = bwd ? neigh[r * KK + (KK - 1)] : neigh[r];
        const float4* src = (const float4*)(table + (size_t)e * FF) + q * 8;
        float4 va[8];
        #pragma unroll
        for (int j = 0; j < 8; j++) va[j] = src[j];   // MLP = 8

        uint32_t* ah = AH + r_l * RSU + q * 16;
        uint32_t* al = AL + r_l * RSU + q * 16;
        #pragma unroll
        for (int j = 0; j < 8; j++) {
            float4 v = va[j];
            __nv_bfloat16 h0 = __float2bfloat16(v.x);
            __nv_bfloat16 h1 = __float2bfloat16(v.y);
            __nv_bfloat16 h2 = __float2bfloat16(v.z);
            __nv_bfloat16 h3 = __float2bfloat16(v.w);
            __nv_bfloat16 l0 = __float2bfloat16(v.x - __bfloat162float(h0));
            __nv_bfloat16 l1 = __float2bfloat16(v.y - __bfloat162float(h1));
            __nv_bfloat16 l2 = __float2bfloat16(v.z - __bfloat162float(h2));
            __nv_bfloat16 l3 = __float2bfloat16(v.w - __bfloat162float(h3));
            ah[j * 2 + 0] = pack2bf(h0, h1);
            ah[j * 2 + 1] = pack2bf(h2, h3);
            al[j * 2 + 0] = pack2bf(l0, l1);
            al[j * 2 + 1] = pack2bf(l2, l3);
        }
    }
    asm volatile("cp.async.wait_group 0;" ::: "memory");
    __syncthreads();

    const uint32_t* BH = smu + BH_OFF;
    const uint32_t* BL = smu + BL_OFF;

    // ---- MMA mainloop ----
    const int w  = tid >> 5;
    const int l  = tid & 31;
    const int wm = w & 3;                  // m-tile (32 rows each)
    const int wn = w >> 2;                 // n-tile (64 cols each)
    const int lr = l >> 2, lc = l & 3;

    float acc[2][8][4];
    #pragma unroll
    for (int mi = 0; mi < 2; mi++)
        #pragma unroll
        for (int ni = 0; ni < 8; ni++)
            #pragma unroll
            for (int i = 0; i < 4; i++) acc[mi][ni][i] = 0.f;

    #pragma unroll
    for (int t = 0; t < 3; t++) {
        const uint32_t* Ab = (t == 1) ? AL : AH;
        const uint32_t* Bb = (t == 2) ? BL : BH;
        #pragma unroll
        for (int ks = 0; ks < 8; ks++) {
            const int kb = ks * 8;         // u32 col base within row
            uint32_t a[2][4];
            #pragma unroll
            for (int mi = 0; mi < 2; mi++) {
                const int br = wm * 32 + mi * 16 + lr;
                a[mi][0] = Ab[(br    ) * RSU + kb     + lc];
                a[mi][1] = Ab[(br + 8) * RSU + kb     + lc];
                a[mi][2] = Ab[(br    ) * RSU + kb + 4 + lc];
                a[mi][3] = Ab[(br + 8) * RSU + kb + 4 + lc];
            }
            #pragma unroll
            for (int ni = 0; ni < 8; ni++) {
                const int n = wn * 64 + ni * 8 + lr;
                uint32_t b0 = Bb[n * RSU + kb + lc];
                uint32_t b1 = Bb[n * RSU + kb + 4 + lc];
                mma16816(acc[0][ni], a[0], b0, b1);
                mma16816(acc[1][ni], a[1], b0, b1);
            }
        }
    }

    // ---- epilogue: +bias, store float2 pairs ----
    float2 bb[8];
    #pragma unroll
    for (int ni = 0; ni < 8; ni++) {
        int c = wn * 64 + ni * 8 + lc * 2;
        bb[ni].x = bih[c] + bhh[c];
        bb[ni].y = bih[c + 1] + bhh[c + 1];
    }
    #pragma unroll
    for (int mi = 0; mi < 2; mi++) {
        const int r = row0 + wm * 32 + mi * 16 + lr;
        #pragma unroll
        for (int ni = 0; ni < 8; ni++) {
            const int c = wn * 64 + ni * 8 + lc * 2;
            if (r < M) {
                float2 v0 = make_float2(acc[mi][ni][0] + bb[ni].x,
                                        acc[mi][ni][1] + bb[ni].y);
                *(float2*)(outp + (size_t)r * GG + c) = v0;
            }
            if (r + 8 < M) {
                float2 v1 = make_float2(acc[mi][ni][2] + bb[ni].x,
                                        acc[mi][ni][3] + bb[ni].y);
                *(float2*)(outp + (size_t)(r + 8) * GG + c) = v1;
            }
        }
    }
}

// ---------------------------------------------------------------------------
// Kernel 2: forward LSTM recurrence on HMMA, register-resident gates.
// CTA = 32 nodes, 256 threads (8 warps) -> ~90 KB smem, regs<=128
// => 2 CTAs/SM: cross-CTA overlap hides per-step barrier + g_xg latency.
// Warp (wm = w&1) owns rows [16wm,16wm+16); warp (wn = w>>1) owns hidden
// cols j in {8wn..8wn+7} u {32+8wn..+7} across all four gate quarters
// (ni = 2q+jg -> col q*64 + jg*32 + wn*8): thread holds i/f/g/o for its
// (node, j) cells in registers. h ping-pongs between 2 SMEM buffers ->
// exactly ONE __syncthreads per step.
// SMEM u32: WH[256][36], WL[256][36], HB[2]{hi[32][36], lo[32][36]}
// ---------------------------------------------------------------------------
#define LNODES 32
#define LW  36
#define WHO 0
#define WLO (256 * LW)                   // 9216
#define HBO (2 * 256 * LW)               // 18432
#define HBSTRIDE (2 * LNODES * LW)       // 2304 u32 per ping-pong buffer (hi+lo)
#define LSTM_SMEM ((HBO + 2 * HBSTRIDE) * 4)   // 92160 B

__global__ __launch_bounds__(256, 2) void lstm_mma_kernel(float* __restrict__ out)
{
    extern __shared__ uint32_t su[];
    uint32_t* WH = su + WHO;
    uint32_t* WL = su + WLO;

    const int tid   = threadIdx.x;
    const int w     = tid >> 5;
    const int l     = tid & 31;
    const int wm    = w & 1;               // row tile: 16 rows
    const int wn    = w >> 1;              // j-octet selector (0..3)
    const int lr    = l >> 2, lc = l & 3;
    const int node0 = blockIdx.x * LNODES;

    // load pre-split Whh (k-contiguous u32 rows of 32)
    {
        const uint32_t* wh = (const uint32_t*)g_Whh_h;
        const uint32_t* wl = (const uint32_t*)g_Whh_l;
        for (int i = tid; i < GG * 32; i += 256) {
            int g = i >> 5, c = i & 31;
            WH[g * LW + c] = wh[i];
            WL[g * LW + c] = wl[i];
        }
    }
    __syncthreads();

    // this thread's rows (local + clamped global)
    const int rloc0 = wm * 16 + lr;        // hf=0 row, local (0..31)
    int nrow[2];
    #pragma unroll
    for (int hf = 0; hf < 2; hf++) {
        int n = node0 + rloc0 + hf * 8;
        nrow[hf] = n < NN ? n : NN - 1;
    }

    // cell state: cst[hf*4 + jg*2 + e]
    float cst[8];
    #pragma unroll
    for (int i = 0; i < 8; i++) cst[i] = 0.f;
    float hout[8];

    for (int k = 0; k < KK; k++) {
        // ---- acc init from g_xg (includes both biases) ----
        float acc[8][4];
        #pragma unroll
        for (int hf = 0; hf < 2; hf++) {
            const float* src = g_xg + ((size_t)nrow[hf] * KK + k) * GG
                             + wn * 8 + lc * 2;
            #pragma unroll
            for (int ni = 0; ni < 8; ni++) {
                const int q = ni >> 1, jg = ni & 1;
                float2 v = *(const float2*)(src + q * 64 + jg * 32);
                acc[ni][hf * 2 + 0] = v.x;
                acc[ni][hf * 2 + 1] = v.y;
            }
        }

        // ---- += h_prev @ Whh^T (3-pass bf16 hi/lo), skip k=0 ----
        if (k > 0) {
            const uint32_t* HHp = su + HBO + (k & 1) * HBSTRIDE;
            const uint32_t* HLp = HHp + LNODES * LW;
            #pragma unroll
            for (int t = 0; t < 3; t++) {
                const uint32_t* Ab = (t == 1) ? HLp : HHp;
                const uint32_t* Bb = (t == 2) ? WL : WH;
                #pragma unroll
                for (int s = 0; s < 4; s++) {
                    const int kb = s * 8;
                    uint32_t a[4];
                    a[0] = Ab[(rloc0    ) * LW + kb     + lc];
                    a[1] = Ab[(rloc0 + 8) * LW + kb     + lc];
                    a[2] = Ab[(rloc0    ) * LW + kb + 4 + lc];
                    a[3] = Ab[(rloc0 + 8) * LW + kb + 4 + lc];
                    #pragma unroll
                    for (int ni = 0; ni < 8; ni++) {
                        const int q = ni >> 1, jg = ni & 1;
                        const int n = q * 64 + jg * 32 + wn * 8 + lr;
                        uint32_t b0 = Bb[n * LW + kb + lc];
                        uint32_t b1 = Bb[n * LW + kb + 4 + lc];
                        mma16816(acc[ni], a, b0, b1);
                    }
                }
            }
        }

        // ---- c/h update entirely in registers; write h to next buffer ----
        uint32_t* HHn = su + HBO + ((k + 1) & 1) * HBSTRIDE;
        uint32_t* HLn = HHn + LNODES * LW;
        #pragma unroll
        for (int hf = 0; hf < 2; hf++) {
            #pragma unroll
            for (int jg = 0; jg < 2; jg++) {
                #pragma unroll
                for (int e = 0; e < 2; e++) {
                    const int idx = hf * 4 + jg * 2 + e;
                    float ig = sigf(acc[0 + jg][hf * 2 + e]);
                    float fg = sigf(acc[2 + jg][hf * 2 + e]);
                    float gz = tanh_fast(acc[4 + jg][hf * 2 + e]);
                    float og = sigf(acc[6 + jg][hf * 2 + e]);
                    cst[idx] = fg * cst[idx] + ig * gz;
                    hout[idx] = og * tanh_fast(cst[idx]);
                }
                float x = hout[hf * 4 + jg * 2], y = hout[hf * 4 + jg * 2 + 1];
                __nv_bfloat16 xh = __float2bfloat16(x);
                __nv_bfloat16 yh = __float2bfloat16(y);
                __nv_bfloat16 xl = __float2bfloat16(x - __bfloat162float(xh));
                __nv_bfloat16 yl = __float2bfloat16(y - __bfloat162float(yh));
                const int a = (rloc0 + hf * 8) * LW + wn * 4 + jg * 16 + lc;
                HHn[a] = pack2bf(xh, yh);
                HLn[a] = pack2bf(xl, yl);
            }
        }
        __syncthreads();   // new h visible before next step's MMA reads

        if (k == KK - 1) {
            #pragma unroll
            for (int hf = 0; hf < 2; hf++) {
                const int n = node0 + rloc0 + hf * 8;
                if (n < NN) {
                    #pragma unroll
                    for (int jg = 0; jg < 2; jg++) {
                        const int j = wn * 8 + jg * 32 + lc * 2;
                        *(float2*)(out + (size_t)n * (2 * HH) + j) =
                            make_float2(hout[hf * 4 + jg * 2],
                                        hout[hf * 4 + jg * 2 + 1]);
                    }
                }
            }
        }
    }

    // ---- backward direction: single cell on x[:, K-1] -> out[n][64:128] ----
    for (int i = tid; i < LNODES * HH; i += 256) {
        int nn = i >> 6, hh2 = i & 63;
        int n = node0 + nn;
        if (n < NN) {
            const float* s = g_xgb + (size_t)n * GG;
            float ig = sigf(s[hh2]);
            float gz = tanh_fast(s[128 + hh2]);
            float og = sigf(s[192 + hh2]);
            float cc = ig * gz;
            out[(size_t)n * (2 * HH) + HH + hh2] = og * tanh_fast(cc);
        }
    }
}

// ---------------------------------------------------------------------------
// Launch. Input order per metadata:
// 0 neigh_idx[N,K] i32, 1 embed_table[V,F] f32,
// 2 Wih_f[256,128], 3 Whh_f[256,64], 4 bih_f[256], 5 bhh_f[256],
// 6 Wih_b[256,128], 7 Whh_b[256,64], 8 bih_b[256], 9 bhh_b[256]
// out: [N, 128] f32
// ---------------------------------------------------------------------------
extern "C" void kernel_launch(void* const* d_in, const int* in_sizes, int n_in,
                              void* d_out, int out_size)
{
    const int*   neigh  = (const int*)  d_in[0];
    const float* table  = (const float*)d_in[1];
    const float* Wih_f  = (const float*)d_in[2];
    const float* Whh_f  = (const float*)d_in[3];
    const float* bih_f  = (const float*)d_in[4];
    const float* bhh_f  = (const float*)d_in[5];
    const float* Wih_b  = (const float*)d_in[6];
    const float* bih_b  = (const float*)d_in[8];
    const float* bhh_b  = (const float*)d_in[9];
    float* out = (float*)d_out;

    (void)in_sizes; (void)n_in; (void)out_size;

    // 0) split weights into bf16 hi/lo (Wih f/b + Whh_f)
    conv_w_kernel<<<128, 256>>>(Wih_f, Wih_b, Whh_f);

    // 1) HMMA gathered projections (cp.async B + batched A gather)
    cudaFuncSetAttribute(proj_mma_kernel,
                         cudaFuncAttributeMaxDynamicSharedMemorySize, PROJ_SMEM);
    proj_mma_kernel<<<(MF + 127) / 128, 512, PROJ_SMEM>>>(neigh, table, bih_f, bhh_f, MF, 0);
    proj_mma_kernel<<<(NN + 127) / 128, 512, PROJ_SMEM>>>(neigh, table, bih_b, bhh_b, NN, 1);

    // 2) HMMA recurrence, 32-node CTAs -> 2 CTAs/SM overlap
    cudaFuncSetAttribute(lstm_mma_kernel,
                         cudaFuncAttributeMaxDynamicSharedMemorySize, LSTM_SMEM);
    lstm_mma_kernel<<<(NN + LNODES - 1) / LNODES, 256, LSTM_SMEM>>>(out);
}